// round 6
// baseline (speedup 1.0000x reference)
#include <cuda_runtime.h>
#include <cuda_bf16.h>
#include <cstdint>

// Problem constants (fixed shapes from reference)
#define T_STEPS 32768
#define D_IN    1024
#define U_HID   1024
#define NG      4096   // 4*U

// ---------------- static device scratch (no allocs allowed) ----------------
__device__ float              g_zx[(size_t)T_STEPS * NG];  // precomputed x@kernel + bias
// packed hidden state: lo32 = h bits, hi32 = step tag. Double-buffered by step parity.
__device__ unsigned long long g_hpk[2][U_HID];

// ============================================================================
// GEMM: zx = x @ kernel + bias   (M=32768, K=1024, N=4096), fp32
// ============================================================================
#define BM 128
#define BN 128
#define BK 16

__global__ __launch_bounds__(256) void gemm_zx(const float* __restrict__ A,
                                               const float* __restrict__ B,
                                               const float* __restrict__ bias) {
    __shared__ float As[2][BK][BM + 4];
    __shared__ float Bs[2][BK][BN];

    const int tid  = threadIdx.x;
    const int cRow = blockIdx.y * BM;
    const int cCol = blockIdx.x * BN;

    const int aRow  = tid >> 2;
    const int aCol4 = tid & 3;
    const int bRow  = tid >> 5;
    const int bCol4 = tid & 31;

    const int tx = tid & 15, ty = tid >> 4;

    const float* Ap = A + (size_t)cRow * D_IN;
    const float* Bp = B + cCol;

    float acc[8][8];
#pragma unroll
    for (int i = 0; i < 8; ++i)
#pragma unroll
        for (int j = 0; j < 8; ++j) acc[i][j] = 0.f;

    float4 ra0, ra1, rb0, rb1;

    auto loadG = [&](int kt) {
        const size_t ac = (size_t)kt * BK + aCol4 * 4;
        ra0 = *(const float4*)&Ap[(size_t)aRow * D_IN + ac];
        ra1 = *(const float4*)&Ap[(size_t)(aRow + 64) * D_IN + ac];
        rb0 = *(const float4*)&Bp[(size_t)(kt * BK + bRow) * NG + bCol4 * 4];
        rb1 = *(const float4*)&Bp[(size_t)(kt * BK + bRow + 8) * NG + bCol4 * 4];
    };
    auto storeS = [&](int buf) {
        const int k0 = aCol4 * 4;
        As[buf][k0 + 0][aRow] = ra0.x; As[buf][k0 + 1][aRow] = ra0.y;
        As[buf][k0 + 2][aRow] = ra0.z; As[buf][k0 + 3][aRow] = ra0.w;
        As[buf][k0 + 0][aRow + 64] = ra1.x; As[buf][k0 + 1][aRow + 64] = ra1.y;
        As[buf][k0 + 2][aRow + 64] = ra1.z; As[buf][k0 + 3][aRow + 64] = ra1.w;
        *(float4*)&Bs[buf][bRow][bCol4 * 4]     = rb0;
        *(float4*)&Bs[buf][bRow + 8][bCol4 * 4] = rb1;
    };

    loadG(0);
    storeS(0);
    __syncthreads();

    const int nT = D_IN / BK;  // 64
    for (int kt = 0; kt < nT; ++kt) {
        const int buf = kt & 1;
        if (kt + 1 < nT) loadG(kt + 1);
#pragma unroll
        for (int k = 0; k < BK; ++k) {
            float4 a0 = *(const float4*)&As[buf][k][ty * 4];
            float4 a1 = *(const float4*)&As[buf][k][64 + ty * 4];
            float4 b0 = *(const float4*)&Bs[buf][k][tx * 4];
            float4 b1 = *(const float4*)&Bs[buf][k][64 + tx * 4];
            float ar[8] = {a0.x, a0.y, a0.z, a0.w, a1.x, a1.y, a1.z, a1.w};
            float br[8] = {b0.x, b0.y, b0.z, b0.w, b1.x, b1.y, b1.z, b1.w};
#pragma unroll
            for (int i = 0; i < 8; ++i)
#pragma unroll
                for (int j = 0; j < 8; ++j)
                    acc[i][j] = fmaf(ar[i], br[j], acc[i][j]);
        }
        if (kt + 1 < nT) storeS(buf ^ 1);
        __syncthreads();
    }

    float4 bv0 = *(const float4*)&bias[cCol + tx * 4];
    float4 bv1 = *(const float4*)&bias[cCol + 64 + tx * 4];
    float bb[8] = {bv0.x, bv0.y, bv0.z, bv0.w, bv1.x, bv1.y, bv1.z, bv1.w};

#pragma unroll
    for (int i = 0; i < 8; ++i) {
        const int r = cRow + ((i < 4) ? (ty * 4 + i) : (64 + ty * 4 + (i - 4)));
        float4 o0 = make_float4(acc[i][0] + bb[0], acc[i][1] + bb[1],
                                acc[i][2] + bb[2], acc[i][3] + bb[3]);
        float4 o1 = make_float4(acc[i][4] + bb[4], acc[i][5] + bb[5],
                                acc[i][6] + bb[6], acc[i][7] + bb[7]);
        *(float4*)&g_zx[(size_t)r * NG + cCol + tx * 4]      = o0;
        *(float4*)&g_zx[(size_t)r * NG + cCol + 64 + tx * 4] = o1;
    }
}

// ============================================================================
// State init (runs every launch: graph replays reuse device globals)
// ============================================================================
__global__ void init_state() {
    const int i = threadIdx.x;
    g_hpk[0][i] = 0ull;                   // h=0, tag=0 -> step 0 matches instantly
    g_hpk[1][i] = 0x8000000000000000ull;  // tag never matches a real step
}

// ============================================================================
// Persistent recurrent kernel. 128 CTAs x 1024 threads, 1 CTA/SM.
// CTA b owns hidden units [8b, 8b+8) => 32 gate-columns.
//   Arrival: lane l of warp w polls packed {h,tag} of element 32w+l (tag match
//            => payload valid in the SAME 8B load). __syncwarp only.
//   Stage 1: lane l = CTA-column (l = 8q+u : gate q, unit u), warp w = rows
//            [32w,32w+32); h via LDS.128 broadcast; fma.rn.f32x2.
//            Partials -> sp[col*33 + w].
//   Stage 2: warp 24+u (high wid = arbiter priority) reduces ALL 4 gates of
//            unit u: quarter q (lanes 8q..8q+7) sums column 8q+u via 4
//            conflict-free LDS + 3 bfly shfls, computes its activation
//            (branch-free), 3 bfly shfls gather i,f,g,o to lane 0, which
//            updates c and publishes h with ONE 8B store. out[] after publish.
//   One __syncthreads per step; sp reuse is ordered by global dataflow
//   (sp(t+1) writes require h(t+1), which requires all sp(t) reads).
// ============================================================================
__global__ __launch_bounds__(1024, 1) void lstm_rec(const float* __restrict__ Rw,
                                                    float* __restrict__ out) {
    const int tid = threadIdx.x;
    const int w   = tid >> 5;
    const int l   = tid & 31;
    const int u0  = blockIdx.x * 8;
    // stage-1 column for lane l (column index within CTA = l = 8q+u)
    const int col = ((l >> 3) << 10) + u0 + (l & 7);

    __shared__ __align__(16) float sh_h[U_HID];
    __shared__ float sp[32 * 33];

    // packed weight pairs: W2[m] = {R[32w+2m][col], R[32w+2m+1][col]}
    unsigned long long W2[16];
    {
        const float* wp = Rw + ((size_t)(w << 5)) * NG + col;
#pragma unroll
        for (int m = 0; m < 16; ++m) {
            float w0 = wp[(size_t)(2 * m) * NG];
            float w1 = wp[(size_t)(2 * m + 1) * NG];
            asm("mov.b64 %0, {%1, %2};" : "=l"(W2[m]) : "f"(w0), "f"(w1));
        }
    }

    // reducer role: warps 24..31, warp 24+u owns unit u0+u
    const bool isRed = (w >= 24);
    const int  u     = w - 24;           // valid when isRed
    const int  q     = l >> 3;           // gate quarter
    const int  j     = l & 7;
    // zx column for this reducer quarter: q*1024 + u0 + u (loaded by j==0)
    const float* zxp = g_zx + ((size_t)q << 10) + u0 + u;

    float cst = 0.f;                     // cell state (lane 0 of reducer warps)
    float zxv = (isRed && j == 0) ? __ldg(zxp) : 0.f;  // zx for t=0

    const int e = (w << 5) + l;          // element this lane polls

    for (int t = 0; t < T_STEPS; ++t) {
        // prefetch next step's zx early (hides DRAM latency under this step)
        float zxn = 0.f;
        if (isRed && j == 0 && t + 1 < T_STEPS)
            zxn = __ldg(&zxp[(size_t)(t + 1) * NG]);

        // poll the packed {h, tag} word; tag==t => h is the step-t value
        {
            const unsigned long long* src = &g_hpk[t & 1][e];
            unsigned long long pk;
            do {
                asm volatile("ld.volatile.global.u64 %0, [%1];"
                             : "=l"(pk) : "l"(src));
            } while ((unsigned)(pk >> 32) != (unsigned)t);
            sh_h[e] = __uint_as_float((unsigned)pk);
        }
        __syncwarp();

        // stage 1: packed-f32x2 partial dot over rows [32w,32w+32) for `col`
        unsigned long long acc0 = 0ull, acc1 = 0ull;
        const ulonglong2* h2 = reinterpret_cast<const ulonglong2*>(sh_h + (w << 5));
#pragma unroll
        for (int k = 0; k < 8; ++k) {
            ulonglong2 hv = h2[k];  // all lanes same address -> smem broadcast
            asm("fma.rn.f32x2 %0, %1, %2, %3;"
                : "=l"(acc0) : "l"(hv.x), "l"(W2[2 * k]),     "l"(acc0));
            asm("fma.rn.f32x2 %0, %1, %2, %3;"
                : "=l"(acc1) : "l"(hv.y), "l"(W2[2 * k + 1]), "l"(acc1));
        }
        float a0, a1, b0, b1;
        asm("mov.b64 {%0, %1}, %2;" : "=f"(a0), "=f"(a1) : "l"(acc0));
        asm("mov.b64 {%0, %1}, %2;" : "=f"(b0), "=f"(b1) : "l"(acc1));
        sp[l * 33 + w] = (a0 + b0) + (a1 + b1);
        __syncthreads();  // the ONLY barrier: all partials in sp

        // stage 2: reducer warps only; everyone else loops straight to poll
        if (isRed) {
            const int c = (q << 3) + u;  // CTA column = 8q+u
            // 4 partials per lane, conflict-free (bank = (c+j+8m)&31)
            const float* spc = sp + c * 33 + j;
            float s = (spc[0] + spc[8]) + (spc[16] + spc[24]);
            if (j == 0) s += zxv;        // fold zx before reduce
            // reduce across the 8-lane quarter
            s += __shfl_xor_sync(0xffffffffu, s, 4);
            s += __shfl_xor_sync(0xffffffffu, s, 2);
            s += __shfl_xor_sync(0xffffffffu, s, 1);
            // branch-free activation: q==2 -> tanh, else sigmoid
            const bool tg = (q == 2);
            const float zc = fminf(fmaxf(s, -15.f), 15.f);
            const float ee = __expf(tg ? (2.f * zc) : (-s));
            const float act = tg ? ((ee - 1.f) / (ee + 1.f))
                                 : (1.f / (1.f + ee));
            // gather i,f,g,o to lane 0 (3 independent bfly shfls)
            const float vf = __shfl_xor_sync(0xffffffffu, act, 8);
            const float vg = __shfl_xor_sync(0xffffffffu, act, 16);
            const float vo = __shfl_xor_sync(0xffffffffu, act, 24);
            if (l == 0) {
                const float c2 = vf * cst + act * vg;   // act = i at lane 0
                cst = c2;
                const float cc = fminf(fmaxf(c2, -15.f), 15.f);
                const float ec = __expf(2.f * cc);
                const float h  = vo * ((ec - 1.f) / (ec + 1.f));
                // publish FIRST: single 8B store carries payload + tag
                unsigned long long pkw;
                asm("mov.b64 %0, {%1, %2};"
                    : "=l"(pkw) : "f"(h), "r"((unsigned)(t + 1)));
                asm volatile("st.volatile.global.u64 [%0], %1;"
                             :: "l"(&g_hpk[(t + 1) & 1][u0 + u]), "l"(pkw)
                             : "memory");
                out[(size_t)t * U_HID + u0 + u] = h;    // off critical path
            }
        }
        zxv = zxn;
    }
}

// ============================================================================
extern "C" void kernel_launch(void* const* d_in, const int* in_sizes, int n_in,
                              void* d_out, int out_size) {
    const float* x    = (const float*)d_in[0];  // [1, 32768, 1024]
    const float* kw   = (const float*)d_in[1];  // [1024, 4096]
    const float* rw   = (const float*)d_in[2];  // [1024, 4096]
    const float* bias = (const float*)d_in[3];  // [4096]
    float* out = (float*)d_out;                 // [1, 32768, 1024]

    dim3 ggrid(NG / BN, T_STEPS / BM);
    gemm_zx<<<ggrid, 256>>>(x, kw, bias);
    init_state<<<1, U_HID>>>();
    lstm_rec<<<128, 1024>>>(rw, out);
}

// round 7
// speedup vs baseline: 2.3250x; 2.3250x over previous
#include <cuda_runtime.h>
#include <cuda_bf16.h>
#include <cstdint>

// Problem constants (fixed shapes from reference)
#define T_STEPS 32768
#define D_IN    1024
#define U_HID   1024
#define NG      4096   // 4*U

// ---------------- static device scratch (no allocs allowed) ----------------
__device__ float              g_zx[(size_t)T_STEPS * NG];  // precomputed x@kernel + bias
// packed hidden state: lo32 = h bits, hi32 = step tag. Double-buffered by step parity.
__device__ unsigned long long g_hpk[2][U_HID];

// ============================================================================
// GEMM: zx = x @ kernel + bias   (M=32768, K=1024, N=4096), fp32
// ============================================================================
#define BM 128
#define BN 128
#define BK 16

__global__ __launch_bounds__(256) void gemm_zx(const float* __restrict__ A,
                                               const float* __restrict__ B,
                                               const float* __restrict__ bias) {
    __shared__ float As[2][BK][BM + 4];
    __shared__ float Bs[2][BK][BN];

    const int tid  = threadIdx.x;
    const int cRow = blockIdx.y * BM;
    const int cCol = blockIdx.x * BN;

    const int aRow  = tid >> 2;
    const int aCol4 = tid & 3;
    const int bRow  = tid >> 5;
    const int bCol4 = tid & 31;

    const int tx = tid & 15, ty = tid >> 4;

    const float* Ap = A + (size_t)cRow * D_IN;
    const float* Bp = B + cCol;

    float acc[8][8];
#pragma unroll
    for (int i = 0; i < 8; ++i)
#pragma unroll
        for (int j = 0; j < 8; ++j) acc[i][j] = 0.f;

    float4 ra0, ra1, rb0, rb1;

    auto loadG = [&](int kt) {
        const size_t ac = (size_t)kt * BK + aCol4 * 4;
        ra0 = *(const float4*)&Ap[(size_t)aRow * D_IN + ac];
        ra1 = *(const float4*)&Ap[(size_t)(aRow + 64) * D_IN + ac];
        rb0 = *(const float4*)&Bp[(size_t)(kt * BK + bRow) * NG + bCol4 * 4];
        rb1 = *(const float4*)&Bp[(size_t)(kt * BK + bRow + 8) * NG + bCol4 * 4];
    };
    auto storeS = [&](int buf) {
        const int k0 = aCol4 * 4;
        As[buf][k0 + 0][aRow] = ra0.x; As[buf][k0 + 1][aRow] = ra0.y;
        As[buf][k0 + 2][aRow] = ra0.z; As[buf][k0 + 3][aRow] = ra0.w;
        As[buf][k0 + 0][aRow + 64] = ra1.x; As[buf][k0 + 1][aRow + 64] = ra1.y;
        As[buf][k0 + 2][aRow + 64] = ra1.z; As[buf][k0 + 3][aRow + 64] = ra1.w;
        *(float4*)&Bs[buf][bRow][bCol4 * 4]     = rb0;
        *(float4*)&Bs[buf][bRow + 8][bCol4 * 4] = rb1;
    };

    loadG(0);
    storeS(0);
    __syncthreads();

    const int nT = D_IN / BK;  // 64
    for (int kt = 0; kt < nT; ++kt) {
        const int buf = kt & 1;
        if (kt + 1 < nT) loadG(kt + 1);
#pragma unroll
        for (int k = 0; k < BK; ++k) {
            float4 a0 = *(const float4*)&As[buf][k][ty * 4];
            float4 a1 = *(const float4*)&As[buf][k][64 + ty * 4];
            float4 b0 = *(const float4*)&Bs[buf][k][tx * 4];
            float4 b1 = *(const float4*)&Bs[buf][k][64 + tx * 4];
            float ar[8] = {a0.x, a0.y, a0.z, a0.w, a1.x, a1.y, a1.z, a1.w};
            float br[8] = {b0.x, b0.y, b0.z, b0.w, b1.x, b1.y, b1.z, b1.w};
#pragma unroll
            for (int i = 0; i < 8; ++i)
#pragma unroll
                for (int j = 0; j < 8; ++j)
                    acc[i][j] = fmaf(ar[i], br[j], acc[i][j]);
        }
        if (kt + 1 < nT) storeS(buf ^ 1);
        __syncthreads();
    }

    float4 bv0 = *(const float4*)&bias[cCol + tx * 4];
    float4 bv1 = *(const float4*)&bias[cCol + 64 + tx * 4];
    float bb[8] = {bv0.x, bv0.y, bv0.z, bv0.w, bv1.x, bv1.y, bv1.z, bv1.w};

#pragma unroll
    for (int i = 0; i < 8; ++i) {
        const int r = cRow + ((i < 4) ? (ty * 4 + i) : (64 + ty * 4 + (i - 4)));
        float4 o0 = make_float4(acc[i][0] + bb[0], acc[i][1] + bb[1],
                                acc[i][2] + bb[2], acc[i][3] + bb[3]);
        float4 o1 = make_float4(acc[i][4] + bb[4], acc[i][5] + bb[5],
                                acc[i][6] + bb[6], acc[i][7] + bb[7]);
        *(float4*)&g_zx[(size_t)r * NG + cCol + tx * 4]      = o0;
        *(float4*)&g_zx[(size_t)r * NG + cCol + 64 + tx * 4] = o1;
    }
}

// ============================================================================
// State init (runs every launch: graph replays reuse device globals)
// ============================================================================
__global__ void init_state() {
    const int i = threadIdx.x;
    g_hpk[0][i] = 0ull;                   // h=0, tag=0 -> step 0 matches instantly
    g_hpk[1][i] = 0x8000000000000000ull;  // tag never matches a real step
}

// ============================================================================
// Persistent recurrent kernel. 128 CTAs x 1024 threads, 1 CTA/SM.
// (structure = R5 proven baseline: 2 barriers/step, all-warp stage 2)
// CTA b owns hidden units [8b, 8b+8) => 32 gate-columns.
//   Arrival: lane l of warp w polls packed {h,tag} of element 32w+l (tag match
//            => payload valid in the SAME 8B load). __syncwarp only.
//   Stage 1: lane l = column, warp w = rows [32w,32w+32); h via LDS.128
//            broadcast; fma.rn.f32x2. Partials -> sp[t&1] (double-buffered:
//            closes the cross-CTA WAR race on sp reuse).
//   Stage 2: warp c reduces column c across 32 warp-partials (shfl) -> zs.
//   Gates:   warp 0, all 32 lanes: lane 8q+u computes activation of gate q,
//            unit u (parallel MUFU), 3 bfly shfls deliver f,g,o to lanes 0-7,
//            which update c and PUBLISH h first (one 8B store), then out[].
// ============================================================================
__global__ __launch_bounds__(1024, 1) void lstm_rec(const float* __restrict__ Rw,
                                                    float* __restrict__ out) {
    const int tid = threadIdx.x;
    const int w   = tid >> 5;
    const int l   = tid & 31;
    const int u0  = blockIdx.x * 8;
    // stage-1 column for lane l; stage-2 column for warp w
    const int col  = ((l >> 3) << 10) + u0 + (l & 7);
    const int col2 = ((w >> 3) << 10) + u0 + (w & 7);

    __shared__ __align__(16) float sh_h[U_HID];
    __shared__ float sp[2][32 * 33];
    __shared__ float zs[32];

    // packed weight pairs: W2[m] = {R[32w+2m][col], R[32w+2m+1][col]}
    unsigned long long W2[16];
    {
        const float* wp = Rw + ((size_t)(w << 5)) * NG + col;
#pragma unroll
        for (int m = 0; m < 16; ++m) {
            float w0 = wp[(size_t)(2 * m) * NG];
            float w1 = wp[(size_t)(2 * m + 1) * NG];
            asm("mov.b64 %0, {%1, %2};" : "=l"(W2[m]) : "f"(w0), "f"(w1));
        }
    }

    float cst = 0.f;                       // cell state (warp 0, lanes 0..7)
    const float* zxp = g_zx + col2;
    float zxv = (l == 0) ? __ldg(zxp) : 0.f;   // zx for t=0

    const int e = (w << 5) + l;            // element this lane polls

    for (int t = 0; t < T_STEPS; ++t) {
        // prefetch next step's zx early (hides DRAM latency under this step)
        float zxn = 0.f;
        if (l == 0 && t + 1 < T_STEPS) zxn = __ldg(&zxp[(size_t)(t + 1) * NG]);

        // poll the packed {h, tag} word; tag==t => h is the step-t value
        {
            const unsigned long long* src = &g_hpk[t & 1][e];
            unsigned long long pk;
            do {
                asm volatile("ld.volatile.global.u64 %0, [%1];"
                             : "=l"(pk) : "l"(src));
            } while ((unsigned)(pk >> 32) != (unsigned)t);
            sh_h[e] = __uint_as_float((unsigned)pk);
        }
        __syncwarp();

        float* const spb = sp[t & 1];      // step-parity buffer (race-free reuse)

        // stage 1: packed-f32x2 partial dot over rows [32w,32w+32) for `col`
        unsigned long long acc0 = 0ull, acc1 = 0ull;
        const ulonglong2* h2 = reinterpret_cast<const ulonglong2*>(sh_h + (w << 5));
#pragma unroll
        for (int k = 0; k < 8; ++k) {
            ulonglong2 hv = h2[k];  // all lanes same address -> smem broadcast
            asm("fma.rn.f32x2 %0, %1, %2, %3;"
                : "=l"(acc0) : "l"(hv.x), "l"(W2[2 * k]),     "l"(acc0));
            asm("fma.rn.f32x2 %0, %1, %2, %3;"
                : "=l"(acc1) : "l"(hv.y), "l"(W2[2 * k + 1]), "l"(acc1));
        }
        float a0, a1, b0, b1;
        asm("mov.b64 {%0, %1}, %2;" : "=f"(a0), "=f"(a1) : "l"(acc0));
        asm("mov.b64 {%0, %1}, %2;" : "=f"(b0), "=f"(b1) : "l"(acc1));
        spb[l * 33 + w] = (a0 + b0) + (a1 + b1);
        __syncthreads();  // bar A: all partials in sp

        // stage 2: warp w reduces its column across 32 warp-partials
        float v = spb[w * 33 + l];
#pragma unroll
        for (int off = 16; off; off >>= 1)
            v += __shfl_xor_sync(0xffffffffu, v, off);
        if (l == 0) zs[w] = v + zxv;
        __syncthreads();  // bar B: gate pre-activations ready

        // gates: warp 0, lane 8q+u computes activation of gate q, unit u
        if (w == 0) {
            const float z  = zs[l];
            const int   q  = l >> 3;
            const bool  tg = (q == 2);
            const float zc = fminf(fmaxf(z, -15.f), 15.f);
            const float ee = __expf(tg ? (2.f * zc) : (-z));
            const float act = tg ? ((ee - 1.f) / (ee + 1.f))
                                 : (1.f / (1.f + ee));
            // deliver f,g,o to lanes 0..7 (3 independent bfly shfls)
            const float vf = __shfl_xor_sync(0xffffffffu, act, 8);
            const float vg = __shfl_xor_sync(0xffffffffu, act, 16);
            const float vo = __shfl_xor_sync(0xffffffffu, act, 24);
            if (l < 8) {
                const float c2 = vf * cst + act * vg;   // act = i on lanes 0..7
                cst = c2;
                const float cc = fminf(fmaxf(c2, -15.f), 15.f);
                const float ec = __expf(2.f * cc);
                const float h  = vo * ((ec - 1.f) / (ec + 1.f));
                // publish FIRST: single 8B store carries payload + tag
                unsigned long long pkw;
                asm("mov.b64 %0, {%1, %2};"
                    : "=l"(pkw) : "f"(h), "r"((unsigned)(t + 1)));
                asm volatile("st.volatile.global.u64 [%0], %1;"
                             :: "l"(&g_hpk[(t + 1) & 1][u0 + l]), "l"(pkw)
                             : "memory");
                out[(size_t)t * U_HID + u0 + l] = h;    // off critical path
            }
        }
        zxv = zxn;
        // no trailing barrier: zs(t+1) writes happen after bar A(t+1), which
        // warp 0 only reaches after gates; sp reuse is parity-buffered.
    }
}

// ============================================================================
extern "C" void kernel_launch(void* const* d_in, const int* in_sizes, int n_in,
                              void* d_out, int out_size) {
    const float* x    = (const float*)d_in[0];  // [1, 32768, 1024]
    const float* kw   = (const float*)d_in[1];  // [1024, 4096]
    const float* rw   = (const float*)d_in[2];  // [1024, 4096]
    const float* bias = (const float*)d_in[3];  // [4096]
    float* out = (float*)d_out;                 // [1, 32768, 1024]

    dim3 ggrid(NG / BN, T_STEPS / BM);
    gemm_zx<<<ggrid, 256>>>(x, kw, bias);
    init_state<<<1, U_HID>>>();
    lstm_rec<<<128, 1024>>>(rw, out);
}